// round 1
// baseline (speedup 1.0000x reference)
#include <cuda_runtime.h>
#include <cuda_bf16.h>
#include <cstdint>

// ---------------------------------------------------------------------------
// SymbolicFeatureExtractor: per-row (seq_len, unique_count) -> 3 feats -> MLP.
// The MLP result depends only on the integer pair (seq_len, uniq), both in
// [0,128], so we precompute a 129x129x32 LUT (2.1 MB, L2-resident) and the
// hot kernel is pure memory streaming + a small shared-mem hash set.
// ---------------------------------------------------------------------------

#define MAX_LEN 128
#define LUT_DIM 129            // seq_len and uniq each in [0,128]

__device__ float g_lut[LUT_DIM * LUT_DIM * 32];

// One warp per (s,u) pair. lane = output index j (and hidden index for layer1).
__global__ __launch_bounds__(256)
void build_lut_kernel(const float* __restrict__ W1, const float* __restrict__ b1,
                      const float* __restrict__ W2, const float* __restrict__ b2) {
    int warp_in_block = threadIdx.x >> 5;
    int lane = threadIdx.x & 31;
    int idx = blockIdx.x * (blockDim.x >> 5) + warp_in_block;   // (s,u) flat index
    if (idx >= LUT_DIM * LUT_DIM) return;
    int s = idx / LUT_DIM;
    int u = idx % LUT_DIM;

    float f0 = (float)s * (1.0f / MAX_LEN);
    float f1 = (float)u * (1.0f / MAX_LEN);
    float f2 = (s > 0) ? ((float)u / (float)s) : 0.0f;

    // h[lane] = relu(f0*W1[0][lane] + f1*W1[1][lane] + f2*W1[2][lane] + b1[lane])
    float h = b1[lane];
    h = fmaf(f0, W1[0 * 32 + lane], h);
    h = fmaf(f1, W1[1 * 32 + lane], h);
    h = fmaf(f2, W1[2 * 32 + lane], h);
    h = fmaxf(h, 0.0f);

    // out[lane] = relu(sum_k h[k] * W2[k][lane] + b2[lane])
    float o = b2[lane];
    #pragma unroll
    for (int k = 0; k < 32; k++) {
        float hk = __shfl_sync(0xffffffffu, h, k);
        o = fmaf(hk, W2[k * 32 + lane], o);
    }
    g_lut[(size_t)idx * 32 + lane] = fmaxf(o, 0.0f);
}

// One warp per row. 8 warps / block. 256-entry shared hash set per warp.
#define WARPS_PER_BLOCK 8
#define HASH_SLOTS 256

__global__ __launch_bounds__(WARPS_PER_BLOCK * 32)
void feat_kernel(const int* __restrict__ ids, const int* __restrict__ mask,
                 float* __restrict__ out, int B) {
    __shared__ int table[WARPS_PER_BLOCK][HASH_SLOTS];

    int w    = threadIdx.x >> 5;
    int lane = threadIdx.x & 31;
    int row  = blockIdx.x * WARPS_PER_BLOCK + w;
    if (row >= B) return;

    int* tab = table[w];
    #pragma unroll
    for (int i = 0; i < HASH_SLOTS / 32; i++)
        tab[lane + 32 * i] = -1;
    __syncwarp();

    const int4* idp = (const int4*)(ids  + (size_t)row * MAX_LEN);
    const int4* mkp = (const int4*)(mask + (size_t)row * MAX_LEN);
    int4 iv = idp[lane];
    int4 mv = mkp[lane];

    int seq = mv.x + mv.y + mv.z + mv.w;    // mask values are 0/1
    int cnt = 0;

    int vals[4] = {iv.x, iv.y, iv.z, iv.w};
    int ms[4]   = {mv.x, mv.y, mv.z, mv.w};

    #pragma unroll
    for (int t = 0; t < 4; t++) {
        if (ms[t]) {
            int v = vals[t];
            unsigned h = ((unsigned)v * 2654435761u) >> 24;   // top 8 bits
            while (true) {
                int old = atomicCAS(&tab[h], -1, v);
                if (old == -1) { cnt++; break; }   // newly inserted -> unique
                if (old == v)  break;              // duplicate
                h = (h + 1) & (HASH_SLOTS - 1);    // linear probe
            }
        }
    }

    seq = __reduce_add_sync(0xffffffffu, seq);
    cnt = __reduce_add_sync(0xffffffffu, cnt);

    // 32 contiguous floats per row, lane-coalesced; LUT is L2-resident.
    out[(size_t)row * 32 + lane] = g_lut[((size_t)(seq * LUT_DIM + cnt)) * 32 + lane];
}

extern "C" void kernel_launch(void* const* d_in, const int* in_sizes, int n_in,
                              void* d_out, int out_size) {
    const int*   ids  = (const int*)d_in[0];
    const int*   mask = (const int*)d_in[1];
    const float* W1   = (const float*)d_in[2];
    const float* b1   = (const float*)d_in[3];
    const float* W2   = (const float*)d_in[4];
    const float* b2   = (const float*)d_in[5];
    float* out = (float*)d_out;

    int B = in_sizes[0] / MAX_LEN;     // 262144

    // LUT: 16641 (s,u) pairs, 8 warps/block -> 2081 blocks.
    int lut_pairs  = LUT_DIM * LUT_DIM;
    int lut_blocks = (lut_pairs + 7) / 8;
    build_lut_kernel<<<lut_blocks, 256>>>(W1, b1, W2, b2);

    int blocks = (B + WARPS_PER_BLOCK - 1) / WARPS_PER_BLOCK;
    feat_kernel<<<blocks, WARPS_PER_BLOCK * 32>>>(ids, mask, out, B);
}

// round 2
// speedup vs baseline: 1.6938x; 1.6938x over previous
#include <cuda_runtime.h>
#include <cuda_bf16.h>
#include <cstdint>

// ---------------------------------------------------------------------------
// SymbolicFeatureExtractor: per-row (seq_len, unique_count) -> 3 feats -> MLP.
// MLP output depends only on the integer pair (seq_len, uniq) in [0,128]^2,
// so a 129x129x32 LUT (2.1 MB, L2-resident) replaces per-row MLP math.
//
// Unique counting: atomic-free iterative scatter. All active tokens plain-STS
// pack(v,pos) to tab[hash_r(v)]; after syncwarp each reads the slot back.
// If the winning word carries my value, my whole value-cohort resolves this
// round (unique counted once, at the winner). Otherwise retry with a new
// round hash. No clears needed: a token only reads a slot it wrote in the
// same round. Guaranteed termination (>=1 cohort resolves per round).
// ---------------------------------------------------------------------------

#define MAX_LEN 128
#define LUT_DIM 129

__device__ float g_lut[LUT_DIM * LUT_DIM * 32];

__global__ __launch_bounds__(256)
void build_lut_kernel(const float* __restrict__ W1, const float* __restrict__ b1,
                      const float* __restrict__ W2, const float* __restrict__ b2) {
    int warp_in_block = threadIdx.x >> 5;
    int lane = threadIdx.x & 31;
    int idx = blockIdx.x * (blockDim.x >> 5) + warp_in_block;
    if (idx >= LUT_DIM * LUT_DIM) return;
    int s = idx / LUT_DIM;
    int u = idx % LUT_DIM;

    float f0 = (float)s * (1.0f / MAX_LEN);
    float f1 = (float)u * (1.0f / MAX_LEN);
    float f2 = (s > 0) ? ((float)u / (float)s) : 0.0f;

    float h = b1[lane];
    h = fmaf(f0, W1[0 * 32 + lane], h);
    h = fmaf(f1, W1[1 * 32 + lane], h);
    h = fmaf(f2, W1[2 * 32 + lane], h);
    h = fmaxf(h, 0.0f);

    float o = b2[lane];
    #pragma unroll
    for (int k = 0; k < 32; k++) {
        float hk = __shfl_sync(0xffffffffu, h, k);
        o = fmaf(hk, W2[k * 32 + lane], o);
    }
    g_lut[(size_t)idx * 32 + lane] = fmaxf(o, 0.0f);
}

#define WARPS_PER_BLOCK 8
#define HASH_SLOTS 256          // 8-bit hash; pack = (v<<8)|pos fits 23 bits

__device__ __forceinline__ unsigned round_hash(int v, unsigned r) {
    return (((unsigned)v ^ (r * 0x9E3779B9u)) * 2654435761u) >> 24;
}

__global__ __launch_bounds__(WARPS_PER_BLOCK * 32)
void feat_kernel(const int* __restrict__ ids, const int* __restrict__ mask,
                 float* __restrict__ out, int B) {
    __shared__ int table[WARPS_PER_BLOCK][HASH_SLOTS];

    int w    = threadIdx.x >> 5;
    int lane = threadIdx.x & 31;
    int row  = blockIdx.x * WARPS_PER_BLOCK + w;
    if (row >= B) return;

    int* tab = table[w];

    const int4* idp = (const int4*)(ids  + (size_t)row * MAX_LEN);
    const int4* mkp = (const int4*)(mask + (size_t)row * MAX_LEN);
    int4 iv = idp[lane];
    int4 mv = mkp[lane];

    int seq = mv.x + mv.y + mv.z + mv.w;

    int vals[4] = {iv.x, iv.y, iv.z, iv.w};
    bool pend[4] = {mv.x != 0, mv.y != 0, mv.z != 0, mv.w != 0};

    int cnt = 0;
    unsigned r = 0;
    while (__ballot_sync(0xffffffffu, pend[0] | pend[1] | pend[2] | pend[3])) {
        unsigned h[4];
        // write phase: every active cohort scatters pack(v,pos) to its slot
        #pragma unroll
        for (int t = 0; t < 4; t++) {
            if (pend[t]) {
                h[t] = round_hash(vals[t], r);
                tab[h[t]] = (vals[t] << 8) | (lane * 4 + t);
            }
        }
        __syncwarp();
        // read phase: resolve cohorts whose value won their slot
        #pragma unroll
        for (int t = 0; t < 4; t++) {
            if (pend[t]) {
                int won = tab[h[t]];
                if ((won >> 8) == vals[t]) {
                    pend[t] = false;
                    if ((won & 255) == lane * 4 + t) cnt++;   // cohort counted once
                }
            }
        }
        __syncwarp();   // next round's writes must not clobber slots mid-read
        r++;
    }

    seq = __reduce_add_sync(0xffffffffu, seq);
    cnt = __reduce_add_sync(0xffffffffu, cnt);

    out[(size_t)row * 32 + lane] = g_lut[((size_t)(seq * LUT_DIM + cnt)) * 32 + lane];
}

extern "C" void kernel_launch(void* const* d_in, const int* in_sizes, int n_in,
                              void* d_out, int out_size) {
    const int*   ids  = (const int*)d_in[0];
    const int*   mask = (const int*)d_in[1];
    const float* W1   = (const float*)d_in[2];
    const float* b1   = (const float*)d_in[3];
    const float* W2   = (const float*)d_in[4];
    const float* b2   = (const float*)d_in[5];
    float* out = (float*)d_out;

    int B = in_sizes[0] / MAX_LEN;

    int lut_pairs  = LUT_DIM * LUT_DIM;
    int lut_blocks = (lut_pairs + 7) / 8;
    build_lut_kernel<<<lut_blocks, 256>>>(W1, b1, W2, b2);

    int blocks = (B + WARPS_PER_BLOCK - 1) / WARPS_PER_BLOCK;
    feat_kernel<<<blocks, WARPS_PER_BLOCK * 32>>>(ids, mask, out, B);
}

// round 3
// speedup vs baseline: 1.9001x; 1.1218x over previous
#include <cuda_runtime.h>
#include <cuda_bf16.h>
#include <cstdint>

// ---------------------------------------------------------------------------
// SymbolicFeatureExtractor: per-row (seq_len, unique_count) -> 3 feats -> MLP.
// MLP output depends only on (seq_len, uniq) in [0,128]^2 -> 129x129x32 LUT
// (2.1 MB, L2-resident; inputs/outputs use streaming hints to protect it).
//
// Unique counting: atomic-free iterative scatter into a 512-slot per-warp
// shared table. pack=(v<<7)|pos written to tab[hash_r(v)]; read-back decides:
//   (won ^ pack) == 0   -> I'm the cohort winner, count 1
//   (won ^ pack) <  128 -> same value won, cohort resolved, no count
//   else                -> different value won this slot, retry next round
// Round-invariant work (h0 = v*K, pack) hoisted; per-round hash is a 9-bit
// field of h0 (shift uniform per round), rehash only every 3rd round.
// No table init needed: a token only reads a slot it wrote in the same round,
// and a same-value stale entry would imply the cohort already resolved.
// ---------------------------------------------------------------------------

#define MAX_LEN 128
#define LUT_DIM 129

__device__ float g_lut[LUT_DIM * LUT_DIM * 32];

__global__ __launch_bounds__(256)
void build_lut_kernel(const float* __restrict__ W1, const float* __restrict__ b1,
                      const float* __restrict__ W2, const float* __restrict__ b2) {
    int warp_in_block = threadIdx.x >> 5;
    int lane = threadIdx.x & 31;
    int idx = blockIdx.x * (blockDim.x >> 5) + warp_in_block;
    if (idx >= LUT_DIM * LUT_DIM) return;
    int s = idx / LUT_DIM;
    int u = idx % LUT_DIM;

    float f0 = (float)s * (1.0f / MAX_LEN);
    float f1 = (float)u * (1.0f / MAX_LEN);
    float f2 = (s > 0) ? ((float)u / (float)s) : 0.0f;

    float h = b1[lane];
    h = fmaf(f0, W1[0 * 32 + lane], h);
    h = fmaf(f1, W1[1 * 32 + lane], h);
    h = fmaf(f2, W1[2 * 32 + lane], h);
    h = fmaxf(h, 0.0f);

    float o = b2[lane];
    #pragma unroll
    for (int k = 0; k < 32; k++) {
        float hk = __shfl_sync(0xffffffffu, h, k);
        o = fmaf(hk, W2[k * 32 + lane], o);
    }
    g_lut[(size_t)idx * 32 + lane] = fmaxf(o, 0.0f);
}

#define WARPS_PER_BLOCK 8
#define HASH_BITS 9
#define HASH_SLOTS (1 << HASH_BITS)   // 512

__global__ __launch_bounds__(WARPS_PER_BLOCK * 32)
void feat_kernel(const int* __restrict__ ids, const int* __restrict__ mask,
                 float* __restrict__ out, int B) {
    __shared__ int table[WARPS_PER_BLOCK][HASH_SLOTS];

    int w    = threadIdx.x >> 5;
    int lane = threadIdx.x & 31;
    int row  = blockIdx.x * WARPS_PER_BLOCK + w;
    if (row >= B) return;

    int* tab = table[w];

    const int4* idp = (const int4*)(ids  + (size_t)row * MAX_LEN);
    const int4* mkp = (const int4*)(mask + (size_t)row * MAX_LEN);
    int4 iv = __ldcs(idp + lane);     // streaming: don't pollute L2 (LUT lives there)
    int4 mv = __ldcs(mkp + lane);

    int seq = mv.x + mv.y + mv.z + mv.w;

    int vals[4] = {iv.x, iv.y, iv.z, iv.w};
    bool pend[4] = {mv.x != 0, mv.y != 0, mv.z != 0, mv.w != 0};

    // Round-invariant per-token precompute.
    unsigned h0[4];
    int pack[4];
    #pragma unroll
    for (int t = 0; t < 4; t++) {
        h0[t]   = (unsigned)vals[t] * 2654435761u;
        pack[t] = (vals[t] << 7) | (lane * 4 + t);   // v<32768 -> fits, pos<128
    }

    int cnt = 0;
    unsigned shift = 32 - HASH_BITS;   // 23, then 14, then 5, then rehash
    while (__ballot_sync(0xffffffffu, pend[0] | pend[1] | pend[2] | pend[3])) {
        unsigned h[4];
        #pragma unroll
        for (int t = 0; t < 4; t++) {
            if (pend[t]) {
                h[t] = (h0[t] >> shift) & (HASH_SLOTS - 1);
                tab[h[t]] = pack[t];
            }
        }
        __syncwarp();
        #pragma unroll
        for (int t = 0; t < 4; t++) {
            if (pend[t]) {
                int x = tab[h[t]] ^ pack[t];
                if (x < 128) {                 // same value won -> cohort resolved
                    pend[t] = false;
                    if (x == 0) cnt++;         // and I'm the canonical winner
                }
            }
        }
        __syncwarp();
        if (shift >= HASH_BITS) {
            shift -= HASH_BITS;
        } else {
            shift = 32 - HASH_BITS;            // rare: fresh hash family
            #pragma unroll
            for (int t = 0; t < 4; t++)
                h0[t] = (h0[t] ^ 0x85EBCA6Bu) * 2654435761u;
        }
    }

    seq = __reduce_add_sync(0xffffffffu, seq);
    cnt = __reduce_add_sync(0xffffffffu, cnt);

    float v = g_lut[((size_t)(seq * LUT_DIM + cnt)) * 32 + lane];
    __stcs(&out[(size_t)row * 32 + lane], v);   // streaming store
}

extern "C" void kernel_launch(void* const* d_in, const int* in_sizes, int n_in,
                              void* d_out, int out_size) {
    const int*   ids  = (const int*)d_in[0];
    const int*   mask = (const int*)d_in[1];
    const float* W1   = (const float*)d_in[2];
    const float* b1   = (const float*)d_in[3];
    const float* W2   = (const float*)d_in[4];
    const float* b2   = (const float*)d_in[5];
    float* out = (float*)d_out;

    int B = in_sizes[0] / MAX_LEN;

    int lut_pairs  = LUT_DIM * LUT_DIM;
    int lut_blocks = (lut_pairs + 7) / 8;
    build_lut_kernel<<<lut_blocks, 256>>>(W1, b1, W2, b2);

    int blocks = (B + WARPS_PER_BLOCK - 1) / WARPS_PER_BLOCK;
    feat_kernel<<<blocks, WARPS_PER_BLOCK * 32>>>(ids, mask, out, B);
}